// round 17
// baseline (speedup 1.0000x reference)
#include <cuda_runtime.h>
#include <cuda_bf16.h>

#define N_NODES 100000
#define N_EDGES 1600000
#define D 64
#define SCAN_B 1024
#define NB_SCAN ((N_NODES + SCAN_B - 1) / SCAN_B)   // 98

typedef unsigned long long ull;

// Scratch (__device__ globals; zero-initialized at load; gather restores the
// zeroed-deg invariant each call so replays stay consistent)
__device__ int   g_deg[N_NODES];
__device__ int   g_off[N_NODES];
__device__ int   g_cursor[N_NODES];
__device__ int   g_bsum[NB_SCAN];
__device__ float g_dinv[N_NODES];
__device__ int   g_csr[N_EDGES];
__device__ float g_z[N_NODES * D];     // Z = diag(dinv) * (X @ W), fp32, 25.6 MB

// ---- packed f32x2 helpers (sm_10x; FFMA2 only reachable via PTX) ----------
__device__ __forceinline__ ull pack2(float lo, float hi) {
    ull r; asm("mov.b64 %0, {%1, %2};" : "=l"(r) : "f"(lo), "f"(hi)); return r;
}
__device__ __forceinline__ ull fma2(ull a, ull b, ull c) {   // a*b + c
    ull d; asm("fma.rn.f32x2 %0, %1, %2, %3;" : "=l"(d) : "l"(a), "l"(b), "l"(c));
    return d;
}
__device__ __forceinline__ ull mul2(ull a, ull b) {
    ull d; asm("mul.rn.f32x2 %0, %1, %2;" : "=l"(d) : "l"(a), "l"(b)); return d;
}

// ---------------------------------------------------------------------------
// 1) in-degree histogram by target — scalar, 1 edge/thread for max TLP
//    (atomic latency hidden by 1.6M-thread parallelism, not per-thread MLP)
// ---------------------------------------------------------------------------
__global__ void degree_kernel(const int* __restrict__ tgt) {
    int e = blockIdx.x * blockDim.x + threadIdx.x;
    if (e < N_EDGES) atomicAdd(&g_deg[tgt[e]], 1);
}

// ---------------------------------------------------------------------------
// 2a) per-block exclusive scan of degrees (block sums to g_bsum) + dinv
// ---------------------------------------------------------------------------
__global__ void scan1_kernel() {
    __shared__ int s[SCAN_B];
    int gid = blockIdx.x * SCAN_B + threadIdx.x;
    int v = (gid < N_NODES) ? g_deg[gid] : 0;
    s[threadIdx.x] = v;
    if (gid < N_NODES) g_dinv[gid] = rsqrtf((float)v);
    __syncthreads();
    for (int ofs = 1; ofs < SCAN_B; ofs <<= 1) {
        int t = (threadIdx.x >= ofs) ? s[threadIdx.x - ofs] : 0;
        __syncthreads();
        s[threadIdx.x] += t;
        __syncthreads();
    }
    if (gid < N_NODES) g_off[gid] = s[threadIdx.x] - v;   // exclusive
    if (threadIdx.x == SCAN_B - 1) g_bsum[blockIdx.x] = s[SCAN_B - 1];
}

// ---------------------------------------------------------------------------
// 2b) fixup: add block prefix (reduced locally) + seed cursor with offset
// ---------------------------------------------------------------------------
__global__ void scan3_kernel() {
    __shared__ int red[256];
    int i = blockIdx.x * 256 + threadIdx.x;
    int j = blockIdx.x >> 2;            // owning scan1 block (1024/256 = 4)
    int v = (threadIdx.x < j) ? g_bsum[threadIdx.x] : 0;   // j <= 97 < 256
    red[threadIdx.x] = v;
    __syncthreads();
    #pragma unroll
    for (int ofs = 128; ofs > 0; ofs >>= 1) {
        if (threadIdx.x < ofs) red[threadIdx.x] += red[threadIdx.x + ofs];
        __syncthreads();
    }
    int bpref = red[0];
    if (i < N_NODES) {
        int o = g_off[i] + bpref;
        g_off[i] = o;
        g_cursor[i] = o;                // fill uses cursor directly as slot
    }
}

// ---------------------------------------------------------------------------
// 3) CSR fill — scalar, 1 edge/thread (TLP over per-thread MLP)
// ---------------------------------------------------------------------------
__global__ void fill_kernel(const int* __restrict__ src,
                            const int* __restrict__ tgt) {
    int e = blockIdx.x * blockDim.x + threadIdx.x;
    if (e < N_EDGES) {
        int t = tgt[e];
        g_csr[atomicAdd(&g_cursor[t], 1)] = src[e];
    }
}

// ---------------------------------------------------------------------------
// 4) Z = diag(dinv) * (X @ W). One thread per node, W smem-broadcast,
//    packed f32x2 FFMA (halves FMA issue count vs scalar FFMA).
// ---------------------------------------------------------------------------
__global__ void __launch_bounds__(256) zgemm_kernel(const float* __restrict__ x,
                                                    const float* __restrict__ W) {
    __shared__ float Ws[D * D];      // 16 KB
    int tid = threadIdx.x;
    for (int i = tid; i < D * D; i += 256) Ws[i] = W[i];
    __syncthreads();

    int node = blockIdx.x * 256 + tid;
    if (node >= N_NODES) return;

    ull acc[32];                      // 64 output cols as 32 packed f32x2
    #pragma unroll
    for (int j = 0; j < 32; j++) acc[j] = 0ULL;   // {0.f, 0.f}

    const float4* xr = (const float4*)(x + (size_t)node * D);
    #pragma unroll 2
    for (int k4 = 0; k4 < 16; k4++) {
        float4 xv = xr[k4];
        float xs[4] = {xv.x, xv.y, xv.z, xv.w};
        #pragma unroll
        for (int kk = 0; kk < 4; kk++) {
            ull xk2 = pack2(xs[kk], xs[kk]);
            const ulonglong2* wrow = (const ulonglong2*)&Ws[(k4 * 4 + kk) * D];
            #pragma unroll
            for (int j = 0; j < 16; j++) {
                ulonglong2 w = wrow[j];           // broadcast LDS.128
                acc[2 * j]     = fma2(xk2, w.x, acc[2 * j]);
                acc[2 * j + 1] = fma2(xk2, w.y, acc[2 * j + 1]);
            }
        }
    }

    float dv = g_dinv[node];
    ull dv2 = pack2(dv, dv);
    ulonglong2* zr = (ulonglong2*)(g_z + (size_t)node * D);
    #pragma unroll
    for (int j = 0; j < 16; j++) {
        ulonglong2 o;
        o.x = mul2(acc[2 * j], dv2);
        o.y = mul2(acc[2 * j + 1], dv2);
        zr[j] = o;                                 // STG.128
    }
}

// ---------------------------------------------------------------------------
// 5) gather: out[t] = relu(dinv_t * sum_{s in N(t)} Z[s] + b)
//    ONE WARP per node (lane owns a float2 chunk): warp-uniform degree loop,
//    no divergence, unroll-8 with batched uniform idx loads -> MLP 8.
//    Also resets g_deg for the next graph replay.
// ---------------------------------------------------------------------------
__global__ void __launch_bounds__(256) gather_kernel(const float* __restrict__ b,
                                                     float* __restrict__ out) {
    int tid  = threadIdx.x;
    int lane = tid & 31;
    int node = blockIdx.x * 8 + (tid >> 5);     // 12500 * 8 = 100000 exactly

    int off = g_off[node];                       // warp-uniform
    int deg = g_deg[node];
    if (lane == 0) g_deg[node] = 0;              // restore zeroed-deg invariant

    const float2* __restrict__ z2 = (const float2*)g_z;   // 32 float2 per row

    float2 acc = make_float2(0.f, 0.f);
    int i = 0;
    for (; i + 8 <= deg; i += 8) {
        int idx[8];
        #pragma unroll
        for (int u = 0; u < 8; u++) idx[u] = g_csr[off + i + u];   // uniform bcast
        #pragma unroll
        for (int u = 0; u < 8; u++) {
            float2 v = z2[(size_t)idx[u] * 32 + lane];             // 8 LDG.64 in flight
            acc.x += v.x; acc.y += v.y;
        }
    }
    int rem = deg - i;
    if (rem > 0) {
        int idx[8];
        #pragma unroll
        for (int u = 0; u < 8; u++)
            idx[u] = (u < rem) ? g_csr[off + i + u] : 0;
        #pragma unroll
        for (int u = 0; u < 8; u++) {
            if (u < rem) {                                         // predicated
                float2 v = z2[(size_t)idx[u] * 32 + lane];
                acc.x += v.x; acc.y += v.y;
            }
        }
    }

    float dn = g_dinv[node];
    float2 bias = ((const float2*)b)[lane];
    float2 o;
    o.x = fmaxf(fmaf(acc.x, dn, bias.x), 0.f);
    o.y = fmaxf(fmaf(acc.y, dn, bias.y), 0.f);
    ((float2*)&out[(size_t)node * D])[lane] = o;
}

// ---------------------------------------------------------------------------
// launch (6 kernels)
// ---------------------------------------------------------------------------
extern "C" void kernel_launch(void* const* d_in, const int* in_sizes, int n_in,
                              void* d_out, int out_size) {
    const float* x   = (const float*)d_in[0];   // [N_NODES, 64]
    const float* W   = (const float*)d_in[1];   // [64, 64]
    const float* b   = (const float*)d_in[2];   // [64]
    const int*   src = (const int*)d_in[3];     // [N_EDGES]
    const int*   tgt = (const int*)d_in[4];     // [N_EDGES]
    float* out = (float*)d_out;                 // [N_NODES, 64]

    degree_kernel<<<(N_EDGES + 255) / 256, 256>>>(tgt);
    scan1_kernel<<<NB_SCAN, SCAN_B>>>();
    scan3_kernel<<<(N_NODES + 255) / 256, 256>>>();
    fill_kernel<<<(N_EDGES + 255) / 256, 256>>>(src, tgt);
    zgemm_kernel<<<(N_NODES + 255) / 256, 256>>>(x, W);
    gather_kernel<<<N_NODES / 8, 256>>>(b, out);
}